// round 15
// baseline (speedup 1.0000x reference)
#include <cuda_runtime.h>
#include <cuda_fp16.h>
#include <cstdint>
#include <cstddef>

#define NN  102400
#define EE  819200
#define DD  128
#define LL  5
#define TSG 1024
#define NCHUNK 400          // NN / 256

// ---------------- scratch (static device globals) ----------------------------
__device__ __half g_hh16[(size_t)NN * DD];       // fp16 activations (gather in)
__device__ __half g_agg16[(size_t)NN * DD];      // MLP input
__device__ __half g_w16t[(size_t)LL * 65536];    // transposed fp16 weights
__device__ int    g_rowptr[NN + 1];
__device__ int    g_cur[NN];                     // invariant: ==0 at call entry/exit
__device__ int    g_bsum[NCHUNK];
__device__ int    g_col[EE];
__device__ float  g_cnt[TSG];
__device__ int    g_off[64];

// ---------------- launch 0: hist + graph prefix -------------------------------
__global__ void histpre_kernel(const int* __restrict__ dst, int E,
                               const int* __restrict__ nsg, int G) {
    int b = blockIdx.x, t = threadIdx.x;
    if (b < 3200) {
        int e = b * 256 + t;
        if (e < E) atomicAdd(&g_cur[dst[e]], 1);
    } else if (t == 0) {
        int a = 0;
        for (int g = 0; g < G; ++g) { g_off[g] = a; a += nsg[g]; }
    }
}

// ---------------- launch 1: scan1 | cnt | x2h | convw | zero ------------------
// block ranges: scan1 [0,400) | cnt [400,800) | x2h [800,13600)
//               convw [13600,14880) | zero [14880,14880+zb)
__global__ void mega2_kernel(const int* __restrict__ batch,
                             const int* __restrict__ sgb, int Nn,
                             const float* __restrict__ x, int total4,
                             const float* __restrict__ W1,
                             const float* __restrict__ W2,
                             float* __restrict__ out, int n_out) {
    int b = blockIdx.x, t = threadIdx.x;
    if (b < 400) {
        __shared__ int s[256];
        int i = b * 256 + t;
        int v = g_cur[i];
        s[t] = v;
        __syncthreads();
#pragma unroll
        for (int o = 1; o < 256; o <<= 1) {
            int u = (t >= o) ? s[t - o] : 0;
            __syncthreads();
            s[t] += u;
            __syncthreads();
        }
        g_rowptr[i] = s[t] - v;
        if (t == 255) g_bsum[b] = s[255];
    } else if (b < 800) {
        int i = (b - 400) * 256 + t;
        if (i < Nn) atomicAdd(&g_cnt[g_off[batch[i]] + sgb[i]], 1.0f);
    } else if (b < 13600) {
        int i = (b - 800) * 256 + t;
        if (i < total4) {
            float4 v = ((const float4*)x)[i];
            __half2 h0 = __floats2half2_rn(v.x, v.y);
            __half2 h1 = __floats2half2_rn(v.z, v.w);
            uint2 o = {*(uint32_t*)&h0, *(uint32_t*)&h1};
            ((uint2*)g_hh16)[i] = o;
        }
    } else if (b < 14880) {
        int i = (b - 13600) * 256 + t;
        int l = i >> 16, r = i & 65535;
        float v;
        if (r < 32768) {
            int n = r >> 7, k = r & 127;
            v = W1[(size_t)l * 32768 + k * 256 + n];
        } else {
            int r2 = r - 32768;
            int n = r2 >> 8, k = r2 & 255;
            v = W2[(size_t)l * 32768 + k * 128 + n];
        }
        g_w16t[i] = __float2half_rn(v);
    } else {
        int i = (b - 14880) * 256 + t;
        if (i < n_out) out[i] = 0.0f;
    }
}

// NOTE: g_cnt is zeroed by... cnt accumulates into g_cnt which must start 0.
// g_cnt zero handled in histpre? No: g_cnt is static __device__ (zero-init at
// module load) BUT the harness replays the graph many times. cnt adds every
// replay -> must zero g_cnt before cnt each call. Handled: cnt block range in
// mega2 runs AFTER histpre; zero g_cnt in histpre (tail block).
// (see histpre2 below)

__global__ void scan23_kernel(int E) {
    __shared__ int s[256];
    int b = blockIdx.x, t = threadIdx.x;
    int partial = 0;
    for (int j = t; j < b; j += 256) partial += g_bsum[j];
    s[t] = partial;
    __syncthreads();
#pragma unroll
    for (int o = 128; o > 0; o >>= 1) {
        if (t < o) s[t] += s[t + o];
        __syncthreads();
    }
    int off = s[0];
    g_rowptr[b * 256 + t] += off;
    if (b == 0 && t == 0) g_rowptr[NN] = E;
}

// self-restoring fill (scalar, high occupancy): drains g_cur back to 0.
__global__ void fill_kernel(const int* __restrict__ src,
                            const int* __restrict__ dst, int E) {
    int e = blockIdx.x * blockDim.x + threadIdx.x;
    if (e >= E) return;
    int d = dst[e];
    int p = g_rowptr[d] + atomicSub(&g_cur[d], 1) - 1;
    g_col[p] = src[e];
}

// ---------------- gather -------------------------------------------------------
__device__ __forceinline__ void acc8(float* acc, uint4 v) {
    const __half2* h = (const __half2*)&v;
#pragma unroll
    for (int j = 0; j < 4; j++) {
        float2 f = __half22float2(h[j]);
        acc[2 * j]     += f.x;
        acc[2 * j + 1] += f.y;
    }
}

__global__ void gather_kernel(const float* __restrict__ eps, int l, int Nn) {
    int gw = (blockIdx.x * blockDim.x + threadIdx.x) >> 5;
    int lane = threadIdx.x & 31;
    int node = gw * 2 + (lane >> 4);
    if (node >= Nn) return;
    int sl = lane & 15;
    float e1 = 1.0f + eps[l];
    const uint4* hv = (const uint4*)g_hh16;

    float acc[8];
    {
        uint4 v = hv[(size_t)node * 16 + sl];
        const __half2* h = (const __half2*)&v;
#pragma unroll
        for (int j = 0; j < 4; j++) {
            float2 f = __half22float2(h[j]);
            acc[2 * j]     = e1 * f.x;
            acc[2 * j + 1] = e1 * f.y;
        }
    }

    int i = g_rowptr[node], t = g_rowptr[node + 1];
    for (; i + 8 <= t; i += 8) {
        int n[8];
#pragma unroll
        for (int j = 0; j < 8; j++) n[j] = g_col[i + j];
        uint4 v[8];
#pragma unroll
        for (int j = 0; j < 8; j++) v[j] = hv[(size_t)n[j] * 16 + sl];
#pragma unroll
        for (int j = 0; j < 8; j++) acc8(acc, v[j]);
    }
    if (i + 4 <= t) {
        int n0 = g_col[i], n1 = g_col[i + 1];
        int n2 = g_col[i + 2], n3 = g_col[i + 3];
        uint4 v0 = hv[(size_t)n0 * 16 + sl];
        uint4 v1 = hv[(size_t)n1 * 16 + sl];
        uint4 v2 = hv[(size_t)n2 * 16 + sl];
        uint4 v3 = hv[(size_t)n3 * 16 + sl];
        acc8(acc, v0); acc8(acc, v1); acc8(acc, v2); acc8(acc, v3);
        i += 4;
    }
    for (; i < t; i++) acc8(acc, hv[(size_t)g_col[i] * 16 + sl]);

    __half2 p0 = __floats2half2_rn(acc[0], acc[1]);
    __half2 p1 = __floats2half2_rn(acc[2], acc[3]);
    __half2 p2 = __floats2half2_rn(acc[4], acc[5]);
    __half2 p3 = __floats2half2_rn(acc[6], acc[7]);
    uint4 o = {*(uint32_t*)&p0, *(uint32_t*)&p1, *(uint32_t*)&p2, *(uint32_t*)&p3};
    ((uint4*)(g_agg16 + (size_t)node * DD))[sl] = o;
}

// ---------------- persistent fused MLP ----------------------------------------
#define CP16(smb, g) \
    asm volatile("cp.async.cg.shared.global [%0], [%1], 16;" :: "r"(smb), "l"(g))
#define W1O 0
#define W2O 69632
#define AO  137216
#define SMEM_TOT 172032

#define LDX4(r0, r1, r2, r3, ad) \
    asm volatile("ldmatrix.sync.aligned.m8n8.x4.shared.b16 {%0,%1,%2,%3}, [%4];" \
                 : "=r"(r0), "=r"(r1), "=r"(r2), "=r"(r3) : "r"(ad))
#define MMA16816(c, a, b0, b1) \
    asm volatile("mma.sync.aligned.m16n8k16.row.col.f32.f16.f16.f32 " \
                 "{%0,%1,%2,%3}, {%4,%5,%6,%7}, {%8,%9}, {%0,%1,%2,%3};" \
                 : "+f"((c)[0]), "+f"((c)[1]), "+f"((c)[2]), "+f"((c)[3]) \
                 : "r"((a)[0]), "r"((a)[1]), "r"((a)[2]), "r"((a)[3]), \
                   "r"(b0), "r"(b1))

__device__ __forceinline__ void red_add_v2(float* p, float2 v) {
    asm volatile("red.global.add.v2.f32 [%0], {%1,%2};"
                 :: "l"(p), "f"(v.x), "f"(v.y) : "memory");
}

__global__ __launch_bounds__(256, 1) void mlp_fused(
    const __half* __restrict__ A, const __half* __restrict__ W1t,
    const float* __restrict__ b1, const __half* __restrict__ W2t,
    const float* __restrict__ b2, __half* __restrict__ H16,
    const int* __restrict__ batch, const int* __restrict__ sgb,
    float* __restrict__ out, int ntiles, int doRelu2, int doPool) {
    extern __shared__ char sm[];
    uint32_t sb  = (uint32_t)__cvta_generic_to_shared(sm);
    uint32_t w1b = sb + W1O, w2b = sb + W2O, ab = sb + AO;

    int tid  = threadIdx.x;
    int lane = tid & 31;
    int wid  = tid >> 5;
    int m0   = wid * 16;
    int stride = gridDim.x;

    for (int i = tid; i < 4096; i += 256) {
        int r = i >> 4, c = i & 15;
        CP16(w1b + r * 272 + c * 16, W1t + (size_t)r * 128 + c * 8);
    }
    {
        int row0 = blockIdx.x * 128;
        for (int i = tid; i < 2048; i += 256) {
            int r = i >> 4, c = i & 15;
            CP16(ab + r * 272 + c * 16, A + (size_t)(row0 + r) * 128 + c * 8);
        }
    }
    asm volatile("cp.async.commit_group;");
    for (int i = tid; i < 4096; i += 256) {
        int r = i >> 5, c = i & 31;
        CP16(w2b + r * 528 + c * 16, W2t + (size_t)r * 256 + c * 8);
    }
    asm volatile("cp.async.commit_group;");
    asm volatile("cp.async.wait_group 1;");
    __syncthreads();

    int g   = lane >> 2;
    int tg  = lane & 3;
    int arow = lane & 15;
    int asel = lane >> 4;
    int brow = (lane & 7) + ((lane >> 4) & 1) * 8;
    int bsel = (lane >> 3) & 1;

    bool firstIter = true;
    for (int tile = blockIdx.x; tile < ntiles; tile += stride) {
        int row0 = tile * 128;
        int nextTile = tile + stride;
        bool hasNext = nextTile < ntiles;

        uint4 pf[8];
        if (hasNext) {
            const uint4* Ag = (const uint4*)(A + (size_t)nextTile * 128 * 128);
#pragma unroll
            for (int j = 0; j < 8; j++) pf[j] = Ag[tid + 256 * j];
        }

        float acc1[32][4];
#pragma unroll
        for (int nt = 0; nt < 32; nt++)
#pragma unroll
            for (int j = 0; j < 4; j++) acc1[nt][j] = 0.0f;

#pragma unroll
        for (int kt = 0; kt < 8; kt++) {
            uint32_t a[4];
            uint32_t ad = ab + (m0 + arow) * 272 + kt * 32 + asel * 16;
            LDX4(a[0], a[1], a[2], a[3], ad);
#pragma unroll
            for (int np = 0; np < 16; np++) {
                uint32_t b0, b1, b2, b3;
                uint32_t bd = w1b + (np * 16 + brow) * 272 + kt * 32 + bsel * 16;
                LDX4(b0, b1, b2, b3, bd);
                MMA16816(acc1[2 * np],     a, b0, b1);
                MMA16816(acc1[2 * np + 1], a, b2, b3);
            }
        }
        if (firstIter) {
            asm volatile("cp.async.wait_group 0;");
            firstIter = false;
        }
        __syncthreads();

        if (hasNext) {
#pragma unroll
            for (int j = 0; j < 8; j++) {
                int i2 = tid + 256 * j;
                int r = i2 >> 4, c = i2 & 15;
                *(uint4*)(sm + AO + r * 272 + c * 16) = pf[j];
            }
        }

        uint32_t yh[16][4];
#pragma unroll
        for (int q = 0; q < 16; q++) {
            int ntA = 2 * q, ntB = 2 * q + 1;
            float2 bvA = *(const float2*)(b1 + ntA * 8 + tg * 2);
            float2 bvB = *(const float2*)(b1 + ntB * 8 + tg * 2);
            float a0 = fmaxf(acc1[ntA][0] + bvA.x, 0.0f);
            float a1 = fmaxf(acc1[ntA][1] + bvA.y, 0.0f);
            float a2 = fmaxf(acc1[ntA][2] + bvA.x, 0.0f);
            float a3 = fmaxf(acc1[ntA][3] + bvA.y, 0.0f);
            float c0 = fmaxf(acc1[ntB][0] + bvB.x, 0.0f);
            float c1 = fmaxf(acc1[ntB][1] + bvB.y, 0.0f);
            float c2 = fmaxf(acc1[ntB][2] + bvB.x, 0.0f);
            float c3 = fmaxf(acc1[ntB][3] + bvB.y, 0.0f);
            __half2 p0 = __floats2half2_rn(a0, a1);
            __half2 p1 = __floats2half2_rn(a2, a3);
            __half2 p2 = __floats2half2_rn(c0, c1);
            __half2 p3 = __floats2half2_rn(c2, c3);
            yh[q][0] = *(uint32_t*)&p0;
            yh[q][1] = *(uint32_t*)&p1;
            yh[q][2] = *(uint32_t*)&p2;
            yh[q][3] = *(uint32_t*)&p3;
        }

        float acc2[16][4];
#pragma unroll
        for (int nt = 0; nt < 16; nt++)
#pragma unroll
            for (int j = 0; j < 4; j++) acc2[nt][j] = 0.0f;

#pragma unroll
        for (int kt = 0; kt < 16; kt++) {
#pragma unroll
            for (int np = 0; np < 8; np++) {
                uint32_t b0, b1x, b2, b3;
                uint32_t bd = w2b + (np * 16 + brow) * 528 + kt * 32 + bsel * 16;
                LDX4(b0, b1x, b2, b3, bd);
                MMA16816(acc2[2 * np],     yh[kt], b0, b1x);
                MMA16816(acc2[2 * np + 1], yh[kt], b2, b3);
            }
        }

        if (doPool) {
            int ra = row0 + m0 + g;
            int sgA = g_off[batch[ra]] + sgb[ra];
            int sgB = g_off[batch[ra + 8]] + sgb[ra + 8];
#pragma unroll
            for (int nt = 0; nt < 16; nt++) {
                int col = nt * 8 + tg * 2;
                float2 bv = *(const float2*)(b2 + col);
                float2 o0 = {acc2[nt][0] + bv.x, acc2[nt][1] + bv.y};
                float2 o1 = {acc2[nt][2] + bv.x, acc2[nt][3] + bv.y};
                red_add_v2(out + (size_t)sgA * DD + col, o0);
                red_add_v2(out + (size_t)sgB * DD + col, o1);
            }
        } else {
            int r0 = row0 + m0 + g;
#pragma unroll
            for (int nt = 0; nt < 16; nt++) {
                int col = nt * 8 + tg * 2;
                float2 bv = *(const float2*)(b2 + col);
                float f0 = acc2[nt][0] + bv.x;
                float f1 = acc2[nt][1] + bv.y;
                float f2 = acc2[nt][2] + bv.x;
                float f3 = acc2[nt][3] + bv.y;
                if (doRelu2) {
                    f0 = fmaxf(f0, 0.0f); f1 = fmaxf(f1, 0.0f);
                    f2 = fmaxf(f2, 0.0f); f3 = fmaxf(f3, 0.0f);
                }
                __half2 p0 = __floats2half2_rn(f0, f1);
                __half2 p1 = __floats2half2_rn(f2, f3);
                *(__half2*)(H16 + (size_t)r0 * DD + col)       = p0;
                *(__half2*)(H16 + (size_t)(r0 + 8) * DD + col) = p1;
            }
        }
        __syncthreads();
    }
}

// ---------------- div ---------------------------------------------------------
__global__ void div_kernel(float* __restrict__ sums, int total) {
    int i = blockIdx.x * blockDim.x + threadIdx.x;
    if (i >= total) return;
    sums[i] /= fmaxf(g_cnt[i / DD], 1.0f);
}

// zero g_cnt tail rider for histpre (separate tiny range)
__global__ void zcnt_kernel() {
    int i = blockIdx.x * blockDim.x + threadIdx.x;
    if (i < TSG) g_cnt[i] = 0.0f;
}

// ---------------- launch ------------------------------------------------------
extern "C" void kernel_launch(void* const* d_in, const int* in_sizes, int n_in,
                              void* d_out, int out_size) {
    const float* x     = (const float*)d_in[0];
    const int*   edge  = (const int*)d_in[1];
    const int*   batch = (const int*)d_in[2];
    const int*   sgb   = (const int*)d_in[3];
    const int*   nsg   = (const int*)d_in[4];
    const float* W1  = (const float*)d_in[5];
    const float* b1  = (const float*)d_in[6];
    const float* W2  = (const float*)d_in[7];
    const float* b2  = (const float*)d_in[8];
    const float* eps = (const float*)d_in[9];
    float* out = (float*)d_out;

    int N = in_sizes[0] / DD;
    int E = in_sizes[1] / 2;
    int G = in_sizes[4];
    const int* src = edge;
    const int* dst = edge + E;

    void *pa, *pw, *ph16;
    cudaGetSymbolAddress(&pa, g_agg16);
    cudaGetSymbolAddress(&pw, g_w16t);
    cudaGetSymbolAddress(&ph16, g_hh16);
    __half* h16   = (__half*)ph16;
    __half* agg16 = (__half*)pa;
    __half* w16t  = (__half*)pw;

    static bool inited = false;
    if (!inited) {
        cudaFuncSetAttribute(mlp_fused,
                             cudaFuncAttributeMaxDynamicSharedMemorySize, SMEM_TOT);
        inited = true;
    }

    int zb = (out_size + 255) / 256;

    // launch 0: zero g_cnt (4 blocks, overlaps with nothing heavy)
    zcnt_kernel<<<4, 256>>>();
    // launch 1: hist + graph prefix
    histpre_kernel<<<3201, 256>>>(dst, E, nsg, G);
    // launch 2: scan1 | cnt | x2h | convw | zero(out)
    mega2_kernel<<<14880 + zb, 256>>>(batch, sgb, N, x, N * DD / 4,
                                      W1, W2, out, out_size);
    // launch 3: scan23
    scan23_kernel<<<NCHUNK, 256>>>(E);
    // launch 4: fill
    fill_kernel<<<(E + 255) / 256, 256>>>(src, dst, E);

    int ntiles = N / 128;
    int grid = 148 < ntiles ? 148 : ntiles;
    int gatherBlocks = (int)(((long long)(N + 1) / 2 * 32 + 255) / 256);

    for (int l = 0; l < LL; l++) {
        gather_kernel<<<gatherBlocks, 256>>>(eps, l, N);
        mlp_fused<<<grid, 256, SMEM_TOT>>>(
            agg16, w16t + (size_t)l * 65536, b1 + (size_t)l * 256,
            w16t + (size_t)l * 65536 + 32768, b2 + (size_t)l * 128,
            h16, batch, sgb, out, ntiles,
            (l < LL - 1) ? 1 : 0, (l == LL - 1) ? 1 : 0);
    }

    div_kernel<<<(out_size + 255) / 256, 256>>>(out, out_size);
}